// round 7
// baseline (speedup 1.0000x reference)
#include <cuda_runtime.h>

// LiquidNeuralNetwork B=256,S=4096,I=32,H=64,O=1 — v7: warp-per-chain scan
// (no cross-warp barriers at all) + fully precomputed input projection.
//
// Algebra: Wc = W_ih@W_in (64x32), cbias = bias + W_ih@b_in
//   ie[b,t,:] = x[b,t,:]@Wc^T + cbias            (precomputed to gmem)
//   h_t+1 = (1-1/tau)*h_t + (1/tau)*(tanh(h_t)@W_hh^T + ie_t)
//   out_t = tanh(h_t+1)@W_out^T + b_out
//
// Scan mapping: 128 CTAs x 64 threads = 2 fully independent warp-chains per
// CTA. Lane l owns hidden units 2l, 2l+1 (W_hh rows resident: 64 f32x2 regs).
// Exchange via smem tanh ring + __syncwarp only. ie streamed from gmem with a
// depth-4 per-lane register pipeline (coalesced LDG.64 per step). Output head
// batched every TC=32 steps from the ring.

#define NB   256
#define SEQ  4096
#define NI   32
#define NH   64
#define TC   32
#define NC   (SEQ / TC)
#define RS   68            // ring row stride (floats): 16B-aligned rows

typedef unsigned long long u64;

__device__ __forceinline__ float2 upk2(u64 v) {
    float2 f; asm("mov.b64 {%0,%1}, %2;" : "=f"(f.x), "=f"(f.y) : "l"(v)); return f;
}
__device__ __forceinline__ u64 pk2(float lo, float hi) {
    u64 r; asm("mov.b64 %0, {%1,%2};" : "=l"(r) : "f"(lo), "f"(hi)); return r;
}
__device__ __forceinline__ u64 fma2(u64 a, u64 b, u64 c) {
    u64 d; asm("fma.rn.f32x2 %0, %1, %2, %3;" : "=l"(d) : "l"(a), "l"(b), "l"(c)); return d;
}
__device__ __forceinline__ u64 add2(u64 a, u64 b) {
    u64 d; asm("add.rn.f32x2 %0, %1, %2;" : "=l"(d) : "l"(a), "l"(b)); return d;
}
__device__ __forceinline__ u64 mul2(u64 a, u64 b) {
    u64 d; asm("mul.rn.f32x2 %0, %1, %2;" : "=l"(d) : "l"(a), "l"(b)); return d;
}
__device__ __forceinline__ float tanh_fast(float x) {
    float y; asm("tanh.approx.f32 %0, %1;" : "=f"(y) : "f"(x)); return y;
}

__device__ float g_Wc[NH * NI];
__device__ float g_cbias[NH];
__device__ float g_ie[(size_t)NB * SEQ * NH];   // 268 MB scratch (module-load alloc)

__global__ void precompute_kernel(const float* __restrict__ W_in,
                                  const float* __restrict__ b_in,
                                  const float* __restrict__ W_ih,
                                  const float* __restrict__ bias)
{
    const int g = threadIdx.x;
    if (g >= NH) return;
    float wih[NH];
#pragma unroll
    for (int h = 0; h < NH; h++) wih[h] = W_ih[g * NH + h];
#pragma unroll 4
    for (int i = 0; i < NI; i++) {
        float s0 = 0.f, s1 = 0.f;
#pragma unroll
        for (int h = 0; h < NH; h += 2) {
            s0 += wih[h + 0] * W_in[(h + 0) * NI + i];
            s1 += wih[h + 1] * W_in[(h + 1) * NI + i];
        }
        g_Wc[g * NI + i] = s0 + s1;
    }
    float cb = bias[g];
#pragma unroll
    for (int h = 0; h < NH; h++) cb += wih[h] * b_in[h];
    g_cbias[g] = cb;
}

// ie[b][t][j] = x[b,t,:] . Wc[j,:] + cbias[j].  64-thread blocks, 64-step tiles.
#define TT 64
__global__ __launch_bounds__(64) void ie_kernel(const float* __restrict__ x)
{
    __shared__ __align__(16) float sx[TT * NI];        // x tile [64 t x 32 i]
    __shared__ __align__(16) float sie[TT][NH + 4];    // transpose buffer (16B rows)

    const int tid = threadIdx.x;
    const int b   = blockIdx.y;
    const int t0  = blockIdx.x * TT;

    const float4* xg = (const float4*)(x + ((size_t)b * SEQ + t0) * NI);
#pragma unroll
    for (int q = 0; q < 8; q++) ((float4*)sx)[q * 64 + tid] = xg[q * 64 + tid];
    __syncthreads();

    const int j = tid;
    float wc[NI];
#pragma unroll
    for (int i = 0; i < NI; i++) wc[i] = g_Wc[j * NI + i];
    const float cb = g_cbias[j];

#pragma unroll 4
    for (int t = 0; t < TT; t++) {
        const float* xr = sx + t * NI;
        float s0 = cb, s1 = 0.f, s2 = 0.f, s3 = 0.f;
#pragma unroll
        for (int i = 0; i < NI; i += 4) {
            s0 += xr[i + 0] * wc[i + 0];
            s1 += xr[i + 1] * wc[i + 1];
            s2 += xr[i + 2] * wc[i + 2];
            s3 += xr[i + 3] * wc[i + 3];
        }
        sie[t][j] = (s0 + s1) + (s2 + s3);
    }
    __syncthreads();

    // Coalesced-ish write-out: thread w writes time row t0+w (64 consecutive floats)
    float4* og = (float4*)(g_ie + ((size_t)b * SEQ + t0 + tid) * NH);
    const float4* sr = (const float4*)sie[tid];
#pragma unroll
    for (int k = 0; k < NH / 4; k++) og[k] = sr[k];
}

__global__ __launch_bounds__(64) void lnn_scan_kernel(
    const float* __restrict__ W_hh,
    const float* __restrict__ tau,
    const float* __restrict__ W_out,
    const float* __restrict__ b_out,
    float* __restrict__ out)
{
    __shared__ __align__(16) float ring[2][(TC + 1) * RS];
    __shared__ float swo[2][NH];

    const int tid = threadIdx.x;
    const int ch  = tid >> 5;          // chain within CTA (independent warps)
    const int l   = tid & 31;          // lane: owns units jA=2l, jB=2l+1
    const int b   = blockIdx.x * 2 + ch;
    const int jA  = 2 * l;

    // Resident packed W_hh rows for both owned units (64 f32x2 regs)
    u64 WA[NH / 2], WB[NH / 2];
    {
        const float* ra = W_hh + jA * NH;
        const float* rb = W_hh + (jA + 1) * NH;
#pragma unroll
        for (int m = 0; m < NH / 2; m++) {
            WA[m] = pk2(ra[2 * m], ra[2 * m + 1]);
            WB[m] = pk2(rb[2 * m], rb[2 * m + 1]);
        }
    }
    const float itA = 1.0f / tau[jA], itB = 1.0f / tau[jA + 1];
    const u64 invt2  = pk2(itA, itB);
    const u64 alpha2 = pk2(1.0f - itA, 1.0f - itB);
    const float bo   = b_out[0];
    swo[ch][jA]     = W_out[jA];
    swo[ch][jA + 1] = W_out[jA + 1];

    // ie stream: float2 per (t, lane); depth-4 register pipeline
    const float2* ieg = (const float2*)(g_ie + (size_t)b * SEQ * NH) + l;
    float2 iepf[4];
#pragma unroll
    for (int d = 0; d < 4; d++) iepf[d] = ieg[d * (NH / 2)];

    u64 h2 = 0ull;                      // packed (hA, hB)
    *(float2*)(ring[ch] + jA) = make_float2(0.f, 0.f);   // row 0 = tanh(h0) = 0
    float* outb = out + (size_t)b * SEQ;
    __syncwarp();

#pragma unroll 1
    for (int c = 0; c < NC; c++) {
#pragma unroll 4
        for (int tt = 0; tt < TC; tt++) {
            const int t = c * TC + tt;

            // hh dots for both units: 16 LDS.128 broadcasts, 64 FFMA2, 8 chains
            const ulonglong2* r2 = (const ulonglong2*)(ring[ch] + tt * RS);
            u64 aA0 = 0ull, aA1 = 0ull, aA2 = 0ull, aA3 = 0ull;
            u64 aB0 = 0ull, aB1 = 0ull, aB2 = 0ull, aB3 = 0ull;
#pragma unroll
            for (int m = 0; m < 8; m++) {
                ulonglong2 v = r2[2 * m];
                ulonglong2 w = r2[2 * m + 1];
                aA0 = fma2(v.x, WA[4 * m + 0], aA0);
                aA1 = fma2(v.y, WA[4 * m + 1], aA1);
                aA2 = fma2(w.x, WA[4 * m + 2], aA2);
                aA3 = fma2(w.y, WA[4 * m + 3], aA3);
                aB0 = fma2(v.x, WB[4 * m + 0], aB0);
                aB1 = fma2(v.y, WB[4 * m + 1], aB1);
                aB2 = fma2(w.x, WB[4 * m + 2], aB2);
                aB3 = fma2(w.y, WB[4 * m + 3], aB3);
            }

            // Consume ie for this step; refill slot for t+4 (clamped at tail)
            const float2 ie2 = iepf[tt & 3];
            int tn = t + 4; if (tn > SEQ - 1) tn = SEQ - 1;
            iepf[tt & 3] = ieg[(size_t)tn * (NH / 2)];

            u64 rA = add2(add2(aA0, aA1), add2(aA2, aA3));
            u64 rB = add2(add2(aB0, aB1), add2(aB2, aB3));
            float2 fA = upk2(rA), fB = upk2(rB);
            const float zA = (fA.x + fA.y) + ie2.x;
            const float zB = (fB.x + fB.y) + ie2.y;

            h2 = fma2(h2, alpha2, mul2(pk2(zA, zB), invt2));   // packed Euler
            float2 hf = upk2(h2);
            float2 th2 = make_float2(tanh_fast(hf.x), tanh_fast(hf.y));
            *(float2*)(ring[ch] + (tt + 1) * RS + jA) = th2;
            __syncwarp();
        }

        // Output head: lane t computes out[c*TC+t] from ring row t+1
        {
            const float* row = ring[ch] + (l + 1) * RS;
            const float* wo  = swo[ch];
            float o0 = bo, o1 = 0.f, o2 = 0.f, o3 = 0.f;
#pragma unroll
            for (int k = 0; k < NH; k += 4) {
                o0 += row[k + 0] * wo[k + 0];
                o1 += row[k + 1] * wo[k + 1];
                o2 += row[k + 2] * wo[k + 2];
                o3 += row[k + 3] * wo[k + 3];
            }
            outb[c * TC + l] = (o0 + o1) + (o2 + o3);
        }
        __syncwarp();
        // Carry row TC -> row 0 for the next chunk
        *(float2*)(ring[ch] + jA) = *(const float2*)(ring[ch] + TC * RS + jA);
        __syncwarp();
    }
}

extern "C" void kernel_launch(void* const* d_in, const int* in_sizes, int n_in,
                              void* d_out, int out_size)
{
    const float* x     = (const float*)d_in[0];
    const float* W_in  = (const float*)d_in[1];
    const float* b_in  = (const float*)d_in[2];
    const float* W_hh  = (const float*)d_in[3];
    const float* W_ih  = (const float*)d_in[4];
    const float* bias  = (const float*)d_in[5];
    const float* tau   = (const float*)d_in[6];
    const float* W_out = (const float*)d_in[7];
    const float* b_out = (const float*)d_in[8];
    float* out = (float*)d_out;

    precompute_kernel<<<1, 64>>>(W_in, b_in, W_ih, bias);
    dim3 g_ie_grid(SEQ / TT, NB);
    ie_kernel<<<g_ie_grid, 64>>>(x);
    lnn_scan_kernel<<<NB / 2, 64>>>(W_hh, tau, W_out, b_out, out);
}